// round 5
// baseline (speedup 1.0000x reference)
#include <cuda_runtime.h>

#define GH 64
#define GW 64
#define NOBJ 16
#define FEAT 256
#define BATCH 4
#define DECAY 0.95f

#define NCELLS (BATCH * GH * GW)         // 16384 cells, 16 rows each
#define ROW_OUT (FEAT + 2)               // 258 floats = 1032 B
#define NBLOCKS 1184                     // 148 SMs * 8 resident blocks

// Persistent kernel: each block grid-strides over cells. Per cell:
//   threads 0..15 compute per-object alpha (parity-double smem buffer) and
//   write the (conf*DECAY, temporal) trailing float2 directly;
//   all 256 threads stream 16x256 features: 4x LDG.128 (streaming), blend,
//   2x STG.64 each (1032B row pitch -> 8B alignment always holds).
__global__ __launch_bounds__(256, 8)
void smg_kernel(const float* __restrict__ grid_state,
                const float* __restrict__ grid_conf,
                const float* __restrict__ grid_temp,
                const float* __restrict__ obj_feat,
                const float* __restrict__ positions,
                const float* __restrict__ occl,
                float* __restrict__ out)
{
    __shared__ float s_alpha[2][NOBJ];

    const int tid = threadIdx.x;
    int p = 0;

    for (int cell = blockIdx.x; cell < NCELLS; cell += NBLOCKS, p ^= 1) {
        const int gw   = cell & (GW - 1);
        const int gh   = (cell >> 6) & (GH - 1);
        const int b    = cell >> 12;
        const int row0 = cell * NOBJ;

        // ---- per-object scalars (threads 0..15) ----
        if (tid < NOBJ) {
            const int o   = tid;
            const int bo  = b * NOBJ + o;
            const int row = row0 + o;
            const float px = positions[bo * 2 + 0];
            const float py = positions[bo * 2 + 1];
            const int gwt = (int)fminf(fmaxf(px * (float)(GW - 1), 0.0f), 63.0f);
            const int ght = (int)fminf(fmaxf(py * (float)(GH - 1), 0.0f), 63.0f);
            const bool upd = (gwt == gw) && (ght == gh);
            const bool vis = occl[bo] < 0.5f;

            s_alpha[p][o] = upd ? (vis ? 0.8f : 0.3f) : 0.0f;

            float c  = grid_conf[row];
            float tm = grid_temp[row];
            if (upd) {
                c  = vis ? fminf(1.0f, c * 0.9f + 0.5f) : c * DECAY;
                tm += vis ? 1.0f : 0.5f;
            }
            __stcs((float2*)(out + (size_t)row * ROW_OUT + FEAT),
                   make_float2(c * DECAY, tm));
        }
        __syncthreads();

        // ---- features: 1024 float4s per cell, 4 per thread ----
        const float4* gs = (const float4*)grid_state + (size_t)row0 * (FEAT / 4);

        float4 v[4];
        #pragma unroll
        for (int j = 0; j < 4; j++)
            v[j] = __ldcs(&gs[tid + 256 * j]);   // front-batched, streaming

        #pragma unroll
        for (int j = 0; j < 4; j++) {
            const int idx = tid + 256 * j;       // 0..1023
            const int rl  = idx >> 6;            // local row (object), warp-uniform
            const int q   = idx & 63;            // float4 index within row
            const float a = s_alpha[p][rl];
            if (a != 0.0f) {                     // warp-uniform, ~never taken
                const int bo = b * NOBJ + rl;
                const float4 o4 = ((const float4*)(obj_feat + (size_t)bo * FEAT))[q];
                const float ia = 1.0f - a;
                v[j].x = a * o4.x + ia * v[j].x;
                v[j].y = a * o4.y + ia * v[j].y;
                v[j].z = a * o4.z + ia * v[j].z;
                v[j].w = a * o4.w + ia * v[j].w;
            }
            float* orow = out + (size_t)(row0 + rl) * ROW_OUT + 4 * q; // 8B aligned
            __stcs((float2*)(orow),     make_float2(v[j].x, v[j].y));
            __stcs((float2*)(orow + 2), make_float2(v[j].z, v[j].w));
        }
        // no trailing sync needed: next iteration writes the other alpha buffer
    }
}

extern "C" void kernel_launch(void* const* d_in, const int* in_sizes, int n_in,
                              void* d_out, int out_size)
{
    const float* grid_state = (const float*)d_in[0];
    const float* grid_conf  = (const float*)d_in[1];
    const float* grid_temp  = (const float*)d_in[2];
    const float* obj_feat   = (const float*)d_in[3];
    const float* positions  = (const float*)d_in[4];
    const float* occl       = (const float*)d_in[5];
    float* out = (float*)d_out;

    smg_kernel<<<NBLOCKS, 256>>>(grid_state, grid_conf, grid_temp,
                                 obj_feat, positions, occl, out);
}

// round 6
// speedup vs baseline: 1.2412x; 1.2412x over previous
#include <cuda_runtime.h>

#define GH 64
#define GW 64
#define NOBJ 16
#define FEAT 256
#define BATCH 4
#define DECAY 0.95f

#define NROWS (BATCH * GH * GW * NOBJ)   // 262144
#define ROW_OUT (FEAT + 2)               // 258 floats = 1032 B
#define RPB NOBJ                         // one cell (16 object-rows) per block

// One block per grid cell (b,gh,gw).
// Order matters: the 4 streaming LDG.128s are issued FIRST (they depend on
// nothing), so phase-0's scattered loads + the barrier overlap their latency.
// Threads 0..15: per-object alpha -> smem, plus the (conf*DECAY, temporal)
// trailing float2 written straight to gmem (no one depends on it -> no extra sync).
__global__ __launch_bounds__(256, 8)
void smg_kernel(const float* __restrict__ grid_state,
                const float* __restrict__ grid_conf,
                const float* __restrict__ grid_temp,
                const float* __restrict__ obj_feat,
                const float* __restrict__ positions,
                const float* __restrict__ occl,
                float* __restrict__ out)
{
    __shared__ float s_alpha[NOBJ];

    const int tid  = threadIdx.x;
    const int cell = blockIdx.x;                 // 0 .. 16383
    const int gw   = cell & (GW - 1);
    const int gh   = (cell >> 6) & (GH - 1);
    const int b    = cell >> 12;
    const int row0 = cell * RPB;

    // ---- Bulk loads first: 4x LDG.128 per thread, front-batched ----
    const float4* gs = (const float4*)grid_state + (size_t)row0 * (FEAT / 4);
    float4 v[4];
    #pragma unroll
    for (int j = 0; j < 4; j++)
        v[j] = gs[tid + 256 * j];

    // ---- Phase 0: per-object scalars (threads 0..15), overlaps load latency ----
    if (tid < NOBJ) {
        const int o   = tid;
        const int bo  = b * NOBJ + o;
        const int row = row0 + o;
        const float px = positions[bo * 2 + 0];
        const float py = positions[bo * 2 + 1];
        const int gwt = (int)fminf(fmaxf(px * (float)(GW - 1), 0.0f), 63.0f);
        const int ght = (int)fminf(fmaxf(py * (float)(GH - 1), 0.0f), 63.0f);
        const bool upd = (gwt == gw) && (ght == gh);
        const bool vis = occl[bo] < 0.5f;

        s_alpha[o] = upd ? (vis ? 0.8f : 0.3f) : 0.0f;

        float c  = grid_conf[row];
        float tm = grid_temp[row];
        if (upd) {
            c  = vis ? fminf(1.0f, c * 0.9f + 0.5f) : c * DECAY;
            tm += vis ? 1.0f : 0.5f;
        }
        // trailing pair at float offset row*258 + 256 (even -> 8B aligned)
        *(float2*)(out + (size_t)row * ROW_OUT + FEAT) = make_float2(c * DECAY, tm);
    }
    __syncthreads();

    // ---- Blend + store: 2x STG.64 per float4 (1032B row pitch, 8B aligned) ----
    #pragma unroll
    for (int j = 0; j < 4; j++) {
        const int idx = tid + 256 * j;           // 0..1023
        const int rl  = idx >> 6;                // local row (object), warp-uniform
        const int q   = idx & 63;                // float4 index within row
        const float a = s_alpha[rl];
        if (a != 0.0f) {                         // warp-uniform, ~never taken
            const int bo = b * NOBJ + rl;
            const float4 o4 = ((const float4*)(obj_feat + (size_t)bo * FEAT))[q];
            const float ia = 1.0f - a;
            v[j].x = a * o4.x + ia * v[j].x;
            v[j].y = a * o4.y + ia * v[j].y;
            v[j].z = a * o4.z + ia * v[j].z;
            v[j].w = a * o4.w + ia * v[j].w;
        }
        float* orow = out + (size_t)(row0 + rl) * ROW_OUT + 4 * q; // 8B aligned
        *(float2*)(orow)     = make_float2(v[j].x, v[j].y);
        *(float2*)(orow + 2) = make_float2(v[j].z, v[j].w);
    }
}

extern "C" void kernel_launch(void* const* d_in, const int* in_sizes, int n_in,
                              void* d_out, int out_size)
{
    const float* grid_state = (const float*)d_in[0];
    const float* grid_conf  = (const float*)d_in[1];
    const float* grid_temp  = (const float*)d_in[2];
    const float* obj_feat   = (const float*)d_in[3];
    const float* positions  = (const float*)d_in[4];
    const float* occl       = (const float*)d_in[5];
    float* out = (float*)d_out;

    smg_kernel<<<NROWS / RPB, 256>>>(grid_state, grid_conf, grid_temp,
                                     obj_feat, positions, occl, out);
}